// round 14
// baseline (speedup 1.0000x reference)
#include <cuda_runtime.h>
#include <cstddef>
#include <cstdint>

// Problem constants (fixed by the reference setup)
#define BATCH 32
#define SEQ   512
#define DIM   1024
#define NCOLS (BATCH * DIM)   // 32768 independent columns
#define CHUNK 8               // scan steps per pipeline stage
#define STAGES 3              // per-warp smem ring depth
#define NCHUNK (SEQ / CHUNK)  // 64
#define WARPS  8              // 256 threads / 32
#define CPW    64             // columns per warp (2 per thread)

// 1.0f / 0.001f correctly rounded = 999.99994f. For sp in {0,1},
// sp / 0.001f == sp * 999.99994f bitwise (1*c and 0*c are exact).
#define SPIKE_OUT 999.99994f

// Float-valued compare. Empirically the fastest exact form on this toolchain
// (r12: 29.1us vs ternary r13: 36.2us) — lowers to a single FSET-class op.
__device__ __forceinline__ float ge1(float a)
{
    float one;
    asm("set.ge.f32.f32 %0, %1, %2;" : "=f"(one) : "f"(a), "f"(1.0f));
    return one;
}

// One scan step = 4 substeps of {v += r; sp = floor(v); v -= sp;}, bitwise-
// faithful. With v in [0,1) and 0 <= r < 1:  a = v + r lies in [0, 2), so
// floor(a) == ge1(a) in {0.0f, 1.0f} and v' = a - ge1(a) is the literal
// reference subtraction. Only the LAST substep's spike survives.
__device__ __forceinline__ float step4(float& v, float r)
{
    #pragma unroll
    for (int i = 0; i < 3; ++i) {
        const float a = v + r;
        v = a - ge1(a);
    }
    const float a   = v + r;
    const float one = ge1(a);
    v = a - one;
    return one * SPIKE_OUT;      // off the chain
}

__global__ __launch_bounds__(256, 1)
void dual_threshold_scan_kernel(const float* __restrict__ inputs,
                                const float* __restrict__ init_state,
                                float* __restrict__ out)
{
    // Per-warp private ring: warp -> stage -> CHUNK rows x 64 cols. 48 KB.
    __shared__ float stage_buf[WARPS][STAGES][CHUNK][CPW];

    const int tid  = threadIdx.x;
    const int wid  = tid >> 5;
    const int lane = tid & 31;

    // 64 blocks; each block covers 512 columns: 2 blocks per batch row.
    const int b_blk = blockIdx.x >> 1;           // batch index
    const int d0    = (blockIdx.x & 1) * 512;    // first dim col of this block

    // Warp w owns columns [d0 + w*64, +64); thread handles cols 2*lane, 2*lane+1.
    // Fetch role: 4 x 16B cp.async per thread per chunk. Round r (0..3):
    // lane L copies 16B of row 2r+(L>>4) at float col (L&15)*4 of the tile.
    const int frow = lane >> 4;                  // 0..1
    const int fseg = (lane & 15) * 4;            // 16B-aligned float offset
    const float* fsrc = inputs + (size_t)b_blk * SEQ * DIM + d0 + wid * CPW + fseg;

    float (&ring)[STAGES][CHUNK][CPW] = stage_buf[wid];

    auto issue_chunk = [&](int c) {
        const int st = c % STAGES;
        #pragma unroll
        for (int r = 0; r < 4; ++r) {
            const float* g = fsrc + (size_t)(c * CHUNK + 2 * r + frow) * DIM;
            uint32_t s = (uint32_t)__cvta_generic_to_shared(
                &ring[st][2 * r + frow][fseg]);
            asm volatile("cp.async.cg.shared.global [%0], [%1], 16;"
                         :: "r"(s), "l"(g));
        }
        asm volatile("cp.async.commit_group;" ::: "memory");
    };

    // Prologue: 16-step lookahead in flight (covers L2-resident latency).
    #pragma unroll
    for (int c = 0; c < STAGES - 1; ++c)
        issue_chunk(c);

    const int col0 = b_blk * DIM + d0 + wid * CPW + 2 * lane;   // global column
    float* __restrict__ op =
        out + (size_t)b_blk * SEQ * DIM + d0 + wid * CPW + 2 * lane;

    float2 vv = *reinterpret_cast<const float2*>(init_state + col0);
    float v0 = vv.x, v1 = vv.y;

    for (int k = 0; k < NCHUNK; ++k) {
        // FIFO: allow STAGES-2 pending groups -> chunk k's group complete,
        // then __syncwarp publishes all lanes' smem writes warp-wide.
        asm volatile("cp.async.wait_group %0;" :: "n"(STAGES - 2) : "memory");
        __syncwarp();

        const int st = k % STAGES;

        // Rates into registers (off the v-chain), LDS.64 per step.
        float2 rr[CHUNK];
        #pragma unroll
        for (int j = 0; j < CHUNK; ++j) {
            const float2 x = *reinterpret_cast<const float2*>(
                &ring[st][j][2 * lane]);
            rr[j].x = fmaxf(x.x, 0.0f) * 0.001f;   // relu * DT
            rr[j].y = fmaxf(x.y, 0.0f) * 0.001f;
        }

        // Two independent serial chains per thread; two warps per SMSP fill
        // each other's latency gaps.
        #pragma unroll
        for (int j = 0; j < CHUNK; ++j) {
            float2 o;
            o.x = step4(v0, rr[j].x);
            o.y = step4(v1, rr[j].y);
            __stcs(reinterpret_cast<float2*>(op + (size_t)(k * CHUNK + j) * DIM), o);
        }

        // WAR on the ring is warp-local: the __syncwarp above ordered this
        // warp's reads of stage (k-1)%STAGES before this refill.
        __syncwarp();
        const int kn = k + STAGES - 1;
        if (kn < NCHUNK) issue_chunk(kn);
        else asm volatile("cp.async.commit_group;" ::: "memory");
    }
}

extern "C" void kernel_launch(void* const* d_in, const int* in_sizes, int n_in,
                              void* d_out, int out_size)
{
    const float* inputs     = (const float*)d_in[0];  // [32, 512, 1024] f32
    const float* init_state = (const float*)d_in[1];  // [32, 1024] f32
    float*       out        = (float*)d_out;          // [32, 512, 1024] f32

    (void)in_sizes; (void)n_in; (void)out_size;

    // 64 blocks x 256 threads x 2 cols/thread = 32768 columns.
    // 2 warps per SMSP, 128 columns per SMSP.
    dual_threshold_scan_kernel<<<64, 256>>>(inputs, init_state, out);
}

// round 15
// speedup vs baseline: 1.5093x; 1.5093x over previous
#include <cuda_runtime.h>
#include <cstddef>
#include <cstdint>

// Problem constants (fixed by the reference setup)
#define BATCH 32
#define SEQ   512
#define DIM   1024
#define NCOLS (BATCH * DIM)   // 32768 independent columns
#define CHUNK 16              // scan steps per pipeline stage
#define STAGES 3              // per-warp smem ring depth
#define NCHUNK (SEQ / CHUNK)  // 32
#define WARPS  7              // 224 threads / 32
#define NBLK   147            // 146 full blocks (224 cols) + 1 tail (64 cols)

// 1.0f / 0.001f correctly rounded = 999.99994f. For sp in {0,1},
// sp / 0.001f == sp * 999.99994f bitwise (1*c and 0*c are exact).
#define SPIKE_OUT 999.99994f

// Float-valued compare. Empirically the fastest exact form on this toolchain
// (r12: 29.1us vs ternary r13: 36.2us).
__device__ __forceinline__ float ge1(float a)
{
    float one;
    asm("set.ge.f32.f32 %0, %1, %2;" : "=f"(one) : "f"(a), "f"(1.0f));
    return one;
}

// One scan step = 4 substeps of {v += r; sp = floor(v); v -= sp;}, bitwise-
// faithful. With v in [0,1) and 0 <= r < 1:  a = v + r lies in [0, 2), so
// floor(a) == ge1(a) in {0.0f, 1.0f} and v' = a - ge1(a) is the literal
// reference subtraction. Only the LAST substep's spike survives.
__device__ __forceinline__ float step4(float& v, float r)
{
    #pragma unroll
    for (int i = 0; i < 3; ++i) {
        const float a = v + r;
        v = a - ge1(a);
    }
    const float a   = v + r;
    const float one = ge1(a);
    v = a - one;
    return one * SPIKE_OUT;      // off the chain
}

__global__ __launch_bounds__(224, 1)
void dual_threshold_scan_kernel(const float* __restrict__ inputs,
                                const float* __restrict__ init_state,
                                float* __restrict__ out)
{
    // Per-warp private ring: warp -> stage -> CHUNK rows x 32 cols. 42 KB.
    __shared__ float stage_buf[WARPS][STAGES][CHUNK][32];

    const int tid  = threadIdx.x;
    const int wid  = tid >> 5;
    const int lane = tid & 31;

    // Warp-uniform column base; tail block's upper warps exit as a unit.
    const int colbase = blockIdx.x * 224 + wid * 32;
    if (colbase >= NCOLS) return;

    // 32-aligned and 32 | 1024 => a warp's 32 cols stay inside one batch row.
    const int b = colbase >> 10;          // batch index
    const int d = colbase & (DIM - 1);    // dim offset of this warp's tile

    // Fetch role: 4 x 16B cp.async per lane per chunk. Round r (0..3):
    // lane L copies 16B of row (L>>3)+4r at float col (L&7)*4 of the tile.
    const int frow  = lane >> 3;          // 0..3
    const int fcol4 = (lane & 7) * 4;     // 16B-aligned float offset
    const float* fsrc = inputs + (size_t)b * SEQ * DIM + d + fcol4;

    float (&ring)[STAGES][CHUNK][32] = stage_buf[wid];

    auto issue_chunk = [&](int c) {
        const int st = c % STAGES;
        #pragma unroll
        for (int r = 0; r < 4; ++r) {
            const float* g = fsrc + (size_t)(c * CHUNK + frow + 4 * r) * DIM;
            uint32_t s = (uint32_t)__cvta_generic_to_shared(
                &ring[st][frow + 4 * r][fcol4]);
            asm volatile("cp.async.cg.shared.global [%0], [%1], 16;"
                         :: "r"(s), "l"(g));
        }
        asm volatile("cp.async.commit_group;" ::: "memory");
    };

    // Prologue: 32-step lookahead in flight.
    #pragma unroll
    for (int c = 0; c < STAGES - 1; ++c)
        issue_chunk(c);

    float* __restrict__ op = out + (size_t)b * SEQ * DIM + d + lane;
    float v = init_state[colbase + lane];

    for (int k = 0; k < NCHUNK; ++k) {
        // FIFO: allow STAGES-2 pending groups -> chunk k's group complete.
        // The single __syncwarp both publishes chunk k's smem writes and
        // orders last iteration's stage reads before this iteration's refill.
        asm volatile("cp.async.wait_group %0;" :: "n"(STAGES - 2) : "memory");
        __syncwarp();

        const int st = k % STAGES;

        // Rates into registers (off the v-chain).
        float rr[CHUNK];
        #pragma unroll
        for (int j = 0; j < CHUNK; ++j)
            rr[j] = fmaxf(ring[st][j][lane], 0.0f) * 0.001f;   // relu * DT

        // Refill early: chunk k+STAGES-1 (stage read in iter k-1; ordered by
        // the syncwarp above). Overlaps cp.async issue with the chain below.
        const int kn = k + STAGES - 1;
        if (kn < NCHUNK) issue_chunk(kn);
        else asm volatile("cp.async.commit_group;" ::: "memory");

        // Pure serial chain; stores off-chain.
        #pragma unroll
        for (int j = 0; j < CHUNK; ++j)
            __stcs(op + (size_t)(k * CHUNK + j) * DIM, step4(v, rr[j]));
    }
}

extern "C" void kernel_launch(void* const* d_in, const int* in_sizes, int n_in,
                              void* d_out, int out_size)
{
    const float* inputs     = (const float*)d_in[0];  // [32, 512, 1024] f32
    const float* init_state = (const float*)d_in[1];  // [32, 1024] f32
    float*       out        = (float*)d_out;          // [32, 512, 1024] f32

    (void)in_sizes; (void)n_in; (void)out_size;

    // 147 blocks x 224 threads: one wave across 147 SMs; 146 blocks cover
    // 224 columns each, block 146 covers the final 64 (upper warps exit).
    dual_threshold_scan_kernel<<<NBLK, 224>>>(inputs, init_state, out);
}